// round 5
// baseline (speedup 1.0000x reference)
#include <cuda_runtime.h>

// Fused bilinear 2x up -> leaky_relu(0.01) -> bilinear 0.5x down == 3x3 stencil.
// x, out: (16, 128, 128, 128) fp32 NHWC.
//
// R4: R3's algebra (2-row blocking, leaky-sum identity) + R2's scheduling.
// R3 regressed because each load fed its hlerp immediately (MLP=1 chain,
// long-scoreboard bound). Here all 4 column loads are batched at the top of
// each iteration (MLP=4), computation follows, slides last.

constexpr int H  = 128;
constexpr int W  = 128;
constexpr int C4 = 32;    // 128 channels / 4
constexpr int STRIP = 16; // output columns per thread

// L = 0.25*a + 0.75*b ; R = 0.75*b + 0.25*c  (t = 0.75*b shared)
__device__ __forceinline__ void hlerp(const float4& a, const float4& b, const float4& c,
                                      float4& L, float4& R) {
    float tx = 0.75f * b.x, ty = 0.75f * b.y, tz = 0.75f * b.z, tw = 0.75f * b.w;
    L = make_float4(fmaf(a.x, 0.25f, tx), fmaf(a.y, 0.25f, ty),
                    fmaf(a.z, 0.25f, tz), fmaf(a.w, 0.25f, tw));
    R = make_float4(fmaf(c.x, 0.25f, tx), fmaf(c.y, 0.25f, ty),
                    fmaf(c.z, 0.25f, tz), fmaf(c.w, 0.25f, tw));
}

__device__ __forceinline__ void vlerp(const float4& v0, const float4& v1, const float4& v2,
                                      float4& U0, float4& U1) {
    float tx = 0.75f * v1.x, ty = 0.75f * v1.y, tz = 0.75f * v1.z, tw = 0.75f * v1.w;
    U0 = make_float4(fmaf(v0.x, 0.25f, tx), fmaf(v0.y, 0.25f, ty),
                     fmaf(v0.z, 0.25f, tz), fmaf(v0.w, 0.25f, tw));
    U1 = make_float4(fmaf(v2.x, 0.25f, tx), fmaf(v2.y, 0.25f, ty),
                     fmaf(v2.z, 0.25f, tz), fmaf(v2.w, 0.25f, tw));
}

// out = 0.25 * sum_k leaky(u_k)  ==  0.12625*sum(u) + 0.12375*sum(|u|)
__device__ __forceinline__ float4 corner_sum(const float4& u00, const float4& u01,
                                             const float4& u10, const float4& u11) {
    float4 r;
    {
        float su = (u00.x + u01.x) + (u10.x + u11.x);
        float sa = (fabsf(u00.x) + fabsf(u01.x)) + (fabsf(u10.x) + fabsf(u11.x));
        r.x = fmaf(su, 0.12625f, 0.12375f * sa);
    }
    {
        float su = (u00.y + u01.y) + (u10.y + u11.y);
        float sa = (fabsf(u00.y) + fabsf(u01.y)) + (fabsf(u10.y) + fabsf(u11.y));
        r.y = fmaf(su, 0.12625f, 0.12375f * sa);
    }
    {
        float su = (u00.z + u01.z) + (u10.z + u11.z);
        float sa = (fabsf(u00.z) + fabsf(u01.z)) + (fabsf(u10.z) + fabsf(u11.z));
        r.z = fmaf(su, 0.12625f, 0.12375f * sa);
    }
    {
        float su = (u00.w + u01.w) + (u10.w + u11.w);
        float sa = (fabsf(u00.w) + fabsf(u01.w)) + (fabsf(u10.w) + fabsf(u11.w));
        r.w = fmaf(su, 0.12625f, 0.12375f * sa);
    }
    return r;
}

__global__ __launch_bounds__(256, 3)
void activation_filter_kernel(const float4* __restrict__ x, float4* __restrict__ out) {
    const int r0 = 2 * blockIdx.x;     // output row pair (r0, r0+1)
    const int r1 = r0 + 1;
    const int b  = blockIdx.y;
    const int tid = threadIdx.x;
    const int c4    = tid & 31;
    const int strip = tid >> 5;        // 0..7, warp-uniform
    const int j0    = strip * STRIP;

    const int im = (r0 > 0)     ? r0 - 1 : 0;
    const int iq = (r1 < H - 1) ? r1 + 1 : H - 1;

    const int img   = b * (H * W * C4);
    const int basec = j0 * C4 + c4;
    const float4* __restrict__ pm = x + img + im * (W * C4) + basec;
    const float4* __restrict__ p0 = x + img + r0 * (W * C4) + basec;
    const float4* __restrict__ p1 = x + img + r1 * (W * C4) + basec;
    const float4* __restrict__ pq = x + img + iq * (W * C4) + basec;
    float4* __restrict__ po0 = out + img + r0 * (W * C4) + basec;
    float4* __restrict__ po1 = out + img + r1 * (W * C4) + basec;

    // window prologue: a = col j-1 (clamped, warp-uniform), b = col j
    // 8 independent loads issued together.
    const int offA = (j0 > 0) ? -C4 : 0;
    float4 a0 = pm[offA], a1 = p0[offA], a2 = p1[offA], a3 = pq[offA];
    float4 b0 = pm[0],    b1 = p0[0],    b2 = p1[0],    b3 = pq[0];

    #pragma unroll 5
    for (int s = 0; s < STRIP - 1; ++s) {
        // ---- all loads first: 4 independent LDG.128 back-to-back ----
        float4 c0 = pm[C4];
        float4 c1 = p0[C4];
        float4 c2 = p1[C4];
        float4 c3 = pq[C4];

        // ---- compute ----
        float4 L0, R0, L1, R1, L2, R2, L3, R3;
        hlerp(a0, b0, c0, L0, R0);
        hlerp(a1, b1, c1, L1, R1);
        hlerp(a2, b2, c2, L2, R2);
        hlerp(a3, b3, c3, L3, R3);

        float4 u00, u10, u01, u11;
        vlerp(L0, L1, L2, u00, u10);       // output row r0: rows (im, r0, r1)
        vlerp(R0, R1, R2, u01, u11);
        __stcs(po0, corner_sum(u00, u01, u10, u11));
        vlerp(L1, L2, L3, u00, u10);       // output row r1: rows (r0, r1, iq)
        vlerp(R1, R2, R3, u01, u11);
        __stcs(po1, corner_sum(u00, u01, u10, u11));

        // ---- slide window ----
        a0 = b0; b0 = c0;
        a1 = b1; b1 = c1;
        a2 = b2; b2 = c2;
        a3 = b3; b3 = c3;
        pm += C4; p0 += C4; p1 += C4; pq += C4; po0 += C4; po1 += C4;
    }

    // final column: only strip 7 clamps (warp-uniform branch)
    {
        float4 c0, c1, c2, c3;
        if (j0 + STRIP < W) {
            c0 = pm[C4]; c1 = p0[C4]; c2 = p1[C4]; c3 = pq[C4];
        } else {
            c0 = b0; c1 = b1; c2 = b2; c3 = b3;
        }
        float4 L0, R0, L1, R1, L2, R2, L3, R3;
        hlerp(a0, b0, c0, L0, R0);
        hlerp(a1, b1, c1, L1, R1);
        hlerp(a2, b2, c2, L2, R2);
        hlerp(a3, b3, c3, L3, R3);

        float4 u00, u10, u01, u11;
        vlerp(L0, L1, L2, u00, u10);
        vlerp(R0, R1, R2, u01, u11);
        __stcs(po0, corner_sum(u00, u01, u10, u11));
        vlerp(L1, L2, L3, u00, u10);
        vlerp(R1, R2, R3, u01, u11);
        __stcs(po1, corner_sum(u00, u01, u10, u11));
    }
}

extern "C" void kernel_launch(void* const* d_in, const int* in_sizes, int n_in,
                              void* d_out, int out_size) {
    const float4* x = (const float4*)d_in[0];
    float4* out = (float4*)d_out;
    dim3 grid(H / 2, 16);   // (output row pair, batch)
    activation_filter_kernel<<<grid, 256>>>(x, out);
}

// round 6
// speedup vs baseline: 1.1676x; 1.1676x over previous
#include <cuda_runtime.h>

// Fused bilinear 2x up -> leaky_relu(0.01) -> bilinear 0.5x down == 3x3 stencil.
// x, out: (16, 128, 128, 128) fp32 NHWC.
//
// R5: R4's algebra (2-row blocking + leaky-sum identity + batched loads) with
// the grid restored to 2048 blocks (R4's 1024-block grid hit ~30% wave
// quantization at 444 resident CTAs: 2.31 -> 3 waves). Each block now does
// one output row-pair x 64 columns; each thread 8 columns x 2 rows.

constexpr int H  = 128;
constexpr int W  = 128;
constexpr int C4 = 32;   // 128 channels / 4
constexpr int STRIP = 8; // output columns per thread

// L = 0.25*a + 0.75*b ; R = 0.75*b + 0.25*c  (t = 0.75*b shared)
__device__ __forceinline__ void hlerp(const float4& a, const float4& b, const float4& c,
                                      float4& L, float4& R) {
    float tx = 0.75f * b.x, ty = 0.75f * b.y, tz = 0.75f * b.z, tw = 0.75f * b.w;
    L = make_float4(fmaf(a.x, 0.25f, tx), fmaf(a.y, 0.25f, ty),
                    fmaf(a.z, 0.25f, tz), fmaf(a.w, 0.25f, tw));
    R = make_float4(fmaf(c.x, 0.25f, tx), fmaf(c.y, 0.25f, ty),
                    fmaf(c.z, 0.25f, tz), fmaf(c.w, 0.25f, tw));
}

__device__ __forceinline__ void vlerp(const float4& v0, const float4& v1, const float4& v2,
                                      float4& U0, float4& U1) {
    float tx = 0.75f * v1.x, ty = 0.75f * v1.y, tz = 0.75f * v1.z, tw = 0.75f * v1.w;
    U0 = make_float4(fmaf(v0.x, 0.25f, tx), fmaf(v0.y, 0.25f, ty),
                     fmaf(v0.z, 0.25f, tz), fmaf(v0.w, 0.25f, tw));
    U1 = make_float4(fmaf(v2.x, 0.25f, tx), fmaf(v2.y, 0.25f, ty),
                     fmaf(v2.z, 0.25f, tz), fmaf(v2.w, 0.25f, tw));
}

// out = 0.25 * sum_k leaky(u_k)  ==  0.12625*sum(u) + 0.12375*sum(|u|)
__device__ __forceinline__ float4 corner_sum(const float4& u00, const float4& u01,
                                             const float4& u10, const float4& u11) {
    float4 r;
    {
        float su = (u00.x + u01.x) + (u10.x + u11.x);
        float sa = (fabsf(u00.x) + fabsf(u01.x)) + (fabsf(u10.x) + fabsf(u11.x));
        r.x = fmaf(su, 0.12625f, 0.12375f * sa);
    }
    {
        float su = (u00.y + u01.y) + (u10.y + u11.y);
        float sa = (fabsf(u00.y) + fabsf(u01.y)) + (fabsf(u10.y) + fabsf(u11.y));
        r.y = fmaf(su, 0.12625f, 0.12375f * sa);
    }
    {
        float su = (u00.z + u01.z) + (u10.z + u11.z);
        float sa = (fabsf(u00.z) + fabsf(u01.z)) + (fabsf(u10.z) + fabsf(u11.z));
        r.z = fmaf(su, 0.12625f, 0.12375f * sa);
    }
    {
        float su = (u00.w + u01.w) + (u10.w + u11.w);
        float sa = (fabsf(u00.w) + fabsf(u01.w)) + (fabsf(u10.w) + fabsf(u11.w));
        r.w = fmaf(su, 0.12625f, 0.12375f * sa);
    }
    return r;
}

__global__ __launch_bounds__(256, 3)
void activation_filter_kernel(const float4* __restrict__ x, float4* __restrict__ out) {
    const int r0 = 2 * blockIdx.x;     // output row pair (r0, r0+1)
    const int r1 = r0 + 1;
    const int half = blockIdx.y;       // width half (0: cols 0..63, 1: 64..127)
    const int b  = blockIdx.z;
    const int tid = threadIdx.x;
    const int c4    = tid & 31;
    const int strip = tid >> 5;        // 0..7, warp-uniform
    const int j0    = half * 64 + strip * STRIP;

    const int im = (r0 > 0)     ? r0 - 1 : 0;
    const int iq = (r1 < H - 1) ? r1 + 1 : H - 1;

    const int img   = b * (H * W * C4);
    const int basec = j0 * C4 + c4;
    const float4* __restrict__ pm = x + img + im * (W * C4) + basec;
    const float4* __restrict__ p0 = x + img + r0 * (W * C4) + basec;
    const float4* __restrict__ p1 = x + img + r1 * (W * C4) + basec;
    const float4* __restrict__ pq = x + img + iq * (W * C4) + basec;
    float4* __restrict__ po0 = out + img + r0 * (W * C4) + basec;
    float4* __restrict__ po1 = out + img + r1 * (W * C4) + basec;

    // window prologue: a = col j0-1 (clamped, warp-uniform), b = col j0
    const int offA = (j0 > 0) ? -C4 : 0;
    float4 a0 = pm[offA], a1 = p0[offA], a2 = p1[offA], a3 = pq[offA];
    float4 b0 = pm[0],    b1 = p0[0],    b2 = p1[0],    b3 = pq[0];

    #pragma unroll
    for (int s = 0; s < STRIP - 1; ++s) {
        // all loads first: 4 independent LDG.128
        float4 c0 = pm[C4];
        float4 c1 = p0[C4];
        float4 c2 = p1[C4];
        float4 c3 = pq[C4];

        float4 L0, R0, L1, R1, L2, R2, L3, R3;
        hlerp(a0, b0, c0, L0, R0);
        hlerp(a1, b1, c1, L1, R1);
        hlerp(a2, b2, c2, L2, R2);
        hlerp(a3, b3, c3, L3, R3);

        float4 u00, u10, u01, u11;
        vlerp(L0, L1, L2, u00, u10);       // output row r0: rows (im, r0, r1)
        vlerp(R0, R1, R2, u01, u11);
        __stcs(po0, corner_sum(u00, u01, u10, u11));
        vlerp(L1, L2, L3, u00, u10);       // output row r1: rows (r0, r1, iq)
        vlerp(R1, R2, R3, u01, u11);
        __stcs(po1, corner_sum(u00, u01, u10, u11));

        a0 = b0; b0 = c0;
        a1 = b1; b1 = c1;
        a2 = b2; b2 = c2;
        a3 = b3; b3 = c3;
        pm += C4; p0 += C4; p1 += C4; pq += C4; po0 += C4; po1 += C4;
    }

    // final column of the strip: only the rightmost strip clamps (warp-uniform)
    {
        float4 c0, c1, c2, c3;
        if (j0 + STRIP < W) {
            c0 = pm[C4]; c1 = p0[C4]; c2 = p1[C4]; c3 = pq[C4];
        } else {
            c0 = b0; c1 = b1; c2 = b2; c3 = b3;
        }
        float4 L0, R0, L1, R1, L2, R2, L3, R3;
        hlerp(a0, b0, c0, L0, R0);
        hlerp(a1, b1, c1, L1, R1);
        hlerp(a2, b2, c2, L2, R2);
        hlerp(a3, b3, c3, L3, R3);

        float4 u00, u10, u01, u11;
        vlerp(L0, L1, L2, u00, u10);
        vlerp(R0, R1, R2, u01, u11);
        __stcs(po0, corner_sum(u00, u01, u10, u11));
        vlerp(L1, L2, L3, u00, u10);
        vlerp(R1, R2, R3, u01, u11);
        __stcs(po1, corner_sum(u00, u01, u10, u11));
    }
}

extern "C" void kernel_launch(void* const* d_in, const int* in_sizes, int n_in,
                              void* d_out, int out_size) {
    const float4* x = (const float4*)d_in[0];
    float4* out = (float4*)d_out;
    dim3 grid(H / 2, 2, 16);   // (row pair, width half, batch) = 2048 blocks
    activation_filter_kernel<<<grid, 256>>>(x, out);
}